// round 10
// baseline (speedup 1.0000x reference)
#include <cuda_runtime.h>
#include <cstdint>
#include <cstddef>

#define B_ 8
#define N_ 4096
#define M_ 4096
#define C_ 256

#define SPLITS 8
#define KM_PER_SPLIT 16      // 16 * 32 = 512 m-rows per split
#define STA 136              // stride (words) for kv's raw-v [32][128] tile
#define PSQ 260              // prep q smem stride (words): 260 mod 32 = 4
#define RST 72               // reduce smem stride (words): 8*tig+g banks distinct

// Scratch (static device arrays; no allocations allowed)
// g_qn: [b][n_tile 32][km 8][kk 4][rt 8][lane 32][w 4]  packed tf32(q*rq/N)
// g_kv: [b][d_tile 2][km 8][kk 4][d8t 16][lane 32][w 2] packed tf32 kv
__device__ uint32_t g_qn[B_ * N_ * C_];
__device__ float    g_rk[B_ * M_];
__device__ float    g_kvp[SPLITS * B_ * C_ * C_];
__device__ uint32_t g_kv[B_ * C_ * C_];

__device__ __forceinline__ uint32_t f2tf(float x) {
    uint32_t r;
    asm("cvt.rna.tf32.f32 %0, %1;" : "=r"(r) : "f"(x));
    return r;
}

__device__ __forceinline__ void mma8(float c[4], const uint32_t a[4], const uint32_t b[2]) {
    asm volatile(
        "mma.sync.aligned.m16n8k8.row.col.f32.tf32.tf32.f32 "
        "{%0,%1,%2,%3}, {%4,%5,%6,%7}, {%8,%9}, {%0,%1,%2,%3};\n"
        : "+f"(c[0]), "+f"(c[1]), "+f"(c[2]), "+f"(c[3])
        : "r"(a[0]), "r"(a[1]), "r"(a[2]), "r"(a[3]),
          "r"(b[0]), "r"(b[1]));
}

__device__ __forceinline__ void cp16(void* smem, const void* gmem) {
    uint32_t s = (uint32_t)__cvta_generic_to_shared(smem);
    asm volatile("cp.async.cg.shared.global [%0], [%1], 16;\n" :: "r"(s), "l"(gmem));
}
__device__ __forceinline__ void cp_commit() { asm volatile("cp.async.commit_group;\n" ::: "memory"); }
template <int NN>
__device__ __forceinline__ void cp_wait() { asm volatile("cp.async.wait_group %0;\n" :: "n"(NN) : "memory"); }

// ---------------------------------------------------------------------------
// Kernel 1a: k row reciprocal norms (tiny output).
// ---------------------------------------------------------------------------
__global__ __launch_bounds__(256) void rnorm_k_kernel(const float* __restrict__ k) {
    const int r = (blockIdx.x * blockDim.x + threadIdx.x) >> 5;
    const int lane = threadIdx.x & 31;
    const float* src = k + (size_t)r * C_;
    float4 a = *(const float4*)(src + lane * 4);
    float4 b = *(const float4*)(src + 128 + lane * 4);
    float ss = a.x * a.x + a.y * a.y + a.z * a.z + a.w * a.w
             + b.x * b.x + b.y * b.y + b.z * b.z + b.w * b.w;
#pragma unroll
    for (int o = 16; o > 0; o >>= 1) ss += __shfl_xor_sync(0xffffffffu, ss, o);
    if (lane == 0) g_rk[r] = (ss > 1e-24f) ? rsqrtf(ss) : 1e12f;
}

// ---------------------------------------------------------------------------
// Kernel 1b: prep q -> packed A-fragments (norm and 1/N folded). Validated R6.
// ---------------------------------------------------------------------------
__global__ __launch_bounds__(256) void prep_q_kernel(const float* __restrict__ q) {
    extern __shared__ float sq[];              // [64][PSQ] + rn[64]
    float* rn = sq + 64 * PSQ;

    const int b    = blockIdx.y;
    const int row0 = blockIdx.x * 64;
    const int t = threadIdx.x, lane = t & 31, wid = t >> 5;

#pragma unroll
    for (int i = 0; i < 8; i++) {
        const int rl = wid * 8 + i;
        const float* src = q + ((size_t)b * N_ + row0 + rl) * C_;
        float4 a = *(const float4*)(src + lane * 4);
        float4 c = *(const float4*)(src + 128 + lane * 4);
        *(float4*)&sq[rl * PSQ + lane * 4]       = a;
        *(float4*)&sq[rl * PSQ + 128 + lane * 4] = c;
        float ss = a.x * a.x + a.y * a.y + a.z * a.z + a.w * a.w
                 + c.x * c.x + c.y * c.y + c.z * c.z + c.w * c.w;
#pragma unroll
        for (int o = 16; o > 0; o >>= 1) ss += __shfl_xor_sync(0xffffffffu, ss, o);
        if (lane == 0) {
            float r = (ss > 1e-24f) ? rsqrtf(ss) : 1e12f;
            rn[rl] = r * (1.0f / (float)N_);
        }
    }
    __syncthreads();

    const int n_tile = blockIdx.x >> 1;
    const int rt_hi  = (blockIdx.x & 1) * 4;
    const int g = lane >> 2, tig = lane & 3;
    uint32_t* obase = g_qn + (size_t)(b * 32 + n_tile) * 32768;

#pragma unroll 1
    for (int it = 0; it < 16; it++) {
        const int bid = it * 8 + wid;
        const int km = bid >> 4, kk = (bid >> 2) & 3, rt = bid & 3;
        const int c0 = km * 32 + kk * 8 + tig;
        const int r0 = rt * 16 + g;
        const float s0 = rn[r0], s1 = rn[r0 + 8];
        uint4 o;
        o.x = f2tf(sq[r0 * PSQ + c0] * s0);
        o.y = f2tf(sq[(r0 + 8) * PSQ + c0] * s1);
        o.z = f2tf(sq[r0 * PSQ + c0 + 4] * s0);
        o.w = f2tf(sq[(r0 + 8) * PSQ + c0 + 4] * s1);
        *(uint4*)&obase[(size_t)(((km * 4 + kk) * 8 + rt_hi + rt) * 128) + lane * 4] = o;
    }
}

// ---------------------------------------------------------------------------
// Kernel 2: split-K partials of kv (validated R7: fused A-pack from raw k).
// ---------------------------------------------------------------------------
__global__ __launch_bounds__(256, 2) void kv_kernel(const float* __restrict__ k,
                                                    const float* __restrict__ v) {
    extern __shared__ uint32_t sm[];
    uint32_t* As = sm;                        // [2][4096] packed A
    float*    Bs = (float*)(sm + 2 * 4096);   // [2][32*STA] raw fp32

    const int bz = blockIdx.z;
    const int b  = bz >> 3;
    const int sp = bz & 7;
    const int c0 = blockIdx.y * 128;
    const int d0 = blockIdx.x * 128;
    const int m_base = sp * (KM_PER_SPLIT * 32);

    const int t = threadIdx.x, lane = t & 31, wid = t >> 5;
    const int g = lane >> 2, tig = lane & 3;
    const int wc = (wid >> 2) * 64;
    const int wd = (wid & 3) * 32;
    const int lr = t >> 3;
    const int lq = (t & 7) * 4;

    const float* kb  = k + (size_t)b * M_ * C_;
    const float* vb  = v + (size_t)b * M_ * C_ + d0;
    const float* rkb = g_rk + b * M_;

    int kkA[4], ctA[4];
#pragma unroll
    for (int i = 0; i < 4; i++) { const int bid = wid * 4 + i; kkA[i] = bid >> 3; ctA[i] = bid & 7; }

    float pv[4][4];
    float pr[4][2];

#define KV_LOAD_A(m0) do { \
    _Pragma("unroll") \
    for (int i = 0; i < 4; i++) { \
        const int mr = (m0) + kkA[i] * 8 + tig; \
        const int cc = c0 + ctA[i] * 16 + g; \
        pv[i][0] = kb[(size_t)mr * C_ + cc]; \
        pv[i][1] = kb[(size_t)mr * C_ + cc + 8]; \
        pv[i][2] = kb[(size_t)(mr + 4) * C_ + cc]; \
        pv[i][3] = kb[(size_t)(mr + 4) * C_ + cc + 8]; \
        pr[i][0] = __ldg(rkb + mr); \
        pr[i][1] = __ldg(rkb + mr + 4); \
    } \
} while (0)

#define KV_STS_A(dst) do { \
    _Pragma("unroll") \
    for (int i = 0; i < 4; i++) { \
        uint4 o; \
        o.x = f2tf(pv[i][0] * pr[i][0]); \
        o.y = f2tf(pv[i][1] * pr[i][0]); \
        o.z = f2tf(pv[i][2] * pr[i][1]); \
        o.w = f2tf(pv[i][3] * pr[i][1]); \
        *(uint4*)&(dst)[(kkA[i] * 8 + ctA[i]) * 128 + lane * 4] = o; \
    } \
} while (0)

    KV_LOAD_A(m_base);
    KV_STS_A(As);
#pragma unroll
    for (int i = 0; i < 4; i++)
        cp16(&Bs[lr * STA + lq + i * 32], vb + (size_t)(m_base + lr) * C_ + lq + i * 32);
    cp_commit();
    KV_LOAD_A(m_base + 32);

    float acc[4][4][4] = {};

#pragma unroll 1
    for (int km = 0; km < KM_PER_SPLIT; km++) {
        const int cur = km & 1;
        const int nxt = cur ^ 1;
        if (km + 1 < KM_PER_SPLIT) {
            const int m0 = m_base + (km + 1) * 32;
            float* Bn = &Bs[nxt * 32 * STA];
#pragma unroll
            for (int i = 0; i < 4; i++)
                cp16(&Bn[lr * STA + lq + i * 32], vb + (size_t)(m0 + lr) * C_ + lq + i * 32);
            cp_commit();
            cp_wait<1>();
        } else {
            cp_wait<0>();
        }
        __syncthreads();

        const uint32_t* Ac = &As[cur * 4096];
        const float*    Bc = &Bs[cur * 32 * STA];
#pragma unroll
        for (int kk = 0; kk < 4; kk++) {
            const int k8 = kk * 8;
            uint32_t af[4][4];
            uint32_t bf[4][2];
#pragma unroll
            for (int mt = 0; mt < 4; mt++) {
                const int rt = (wid >> 2) * 4 + mt;
                const uint4 pk = *(const uint4*)&Ac[(kk * 8 + rt) * 128 + lane * 4];
                af[mt][0] = pk.x; af[mt][1] = pk.y; af[mt][2] = pk.z; af[mt][3] = pk.w;
            }
#pragma unroll
            for (int nt = 0; nt < 4; nt++) {
                const int col = wd + nt * 8 + g;
                bf[nt][0] = f2tf(Bc[(k8 + tig) * STA + col]);
                bf[nt][1] = f2tf(Bc[(k8 + tig + 4) * STA + col]);
            }
#pragma unroll
            for (int mt = 0; mt < 4; mt++)
#pragma unroll
                for (int nt = 0; nt < 4; nt++)
                    mma8(acc[mt][nt], af[mt], bf[nt]);
        }

        if (km + 1 < KM_PER_SPLIT) {
            KV_STS_A(&As[nxt * 4096]);
            if (km + 2 < KM_PER_SPLIT) KV_LOAD_A(m_base + (km + 2) * 32);
        }
        __syncthreads();
    }

    float* kvp = g_kvp + ((size_t)sp * B_ + b) * C_ * C_;
#pragma unroll
    for (int mt = 0; mt < 4; mt++)
#pragma unroll
        for (int nt = 0; nt < 4; nt++) {
            const int c = c0 + wc + mt * 16 + g;
            const int d = d0 + wd + nt * 8 + tig * 2;
            float2 v0 = make_float2(acc[mt][nt][0], acc[mt][nt][1]);
            float2 v1 = make_float2(acc[mt][nt][2], acc[mt][nt][3]);
            *(float2*)&kvp[(size_t)c * C_ + d]       = v0;
            *(float2*)&kvp[(size_t)(c + 8) * C_ + d] = v1;
        }
}

// ---------------------------------------------------------------------------
// Kernel 2b: reduce partials -> packed tf32 B-frags, SMEM-staged.
// CTA per (d-64-block, b). Phase 1: coalesced float4 accumulate into
// [256c][64d] tile (stride RST=72). Phase 2: conflict-free packed emit.
// ---------------------------------------------------------------------------
__global__ __launch_bounds__(256) void reduce_kernel() {
    extern __shared__ float rsm[];             // [256][RST]
    const int dq = blockIdx.x;                 // 0..3 (64-d block)
    const int b  = blockIdx.y;
    const int t = threadIdx.x, lane = t & 31, wid = t >> 5;

    // phase 1: accumulate
#pragma unroll 1
    for (int p = 0; p < 16; p++) {
        const int idx = p * 256 + t;
        const int c   = idx >> 4;
        const int dl4 = (idx & 15) * 4;
        float4 a = make_float4(0.f, 0.f, 0.f, 0.f);
#pragma unroll
        for (int sp = 0; sp < SPLITS; sp++) {
            const float4 x = *(const float4*)&g_kvp[((size_t)(sp * B_ + b) << 16)
                                                    + (size_t)c * C_ + dq * 64 + dl4];
            a.x += x.x; a.y += x.y; a.z += x.z; a.w += x.w;
        }
        *(float4*)&rsm[c * RST + dl4] = a;
    }
    __syncthreads();

    // phase 2: emit packed (dt = dq>>1, d8t = (dq&1)*8 + wid)
    const int g = lane >> 2, tig = lane & 3;
    const int dt  = dq >> 1;
    const int d8t = (dq & 1) * 8 + wid;
    const int dl  = wid * 8 + g;
#pragma unroll
    for (int km = 0; km < 8; km++)
#pragma unroll
        for (int kk = 0; kk < 4; kk++) {
            const int c = km * 32 + kk * 8 + tig;
            uint2 o;
            o.x = f2tf(rsm[c * RST + dl]);
            o.y = f2tf(rsm[(c + 4) * RST + dl]);
            const int idx = (b << 15) | (dt << 14) | (km << 11) | (kk << 9)
                          | (d8t << 5) | lane;
            *(uint2*)&g_kv[(size_t)idx * 2] = o;
        }
}

// ---------------------------------------------------------------------------
// Kernel 3: ctx GEMM, packed operands, 3-stage cp.async ring, ONE sync/iter.
// Order per iter: wait -> sync -> issue(s+2) -> MMA(s). Buffer (s+2)%3 was
// consumed at iter s-1, before this iter's sync -> overwrite-safe.
// ---------------------------------------------------------------------------
__global__ __launch_bounds__(256, 2) void ctx_kernel(float* __restrict__ out) {
    extern __shared__ uint32_t sm[];
    uint32_t* As = sm;              // [3][4096]
    uint32_t* Bs = sm + 3 * 4096;   // [3][4096]

    const int b  = blockIdx.z;
    const int n_tile = blockIdx.y;
    const int dt = blockIdx.x;
    const int n0 = n_tile * 128;
    const int d0 = dt * 128;

    const int t = threadIdx.x, lane = t & 31, wid = t >> 5;
    const int g = lane >> 2, tig = lane & 3;
    const int wn = (wid >> 2) * 64;
    const int wd = (wid & 3) * 32;

    const uint32_t* qb  = g_qn + (size_t)(b * 32 + n_tile) * 32768;
    const uint32_t* kvb = g_kv + (size_t)(b * 2 + dt) * 32768;

#define CTX_ISSUE(s) do { \
        const int _j = (s) % 3; \
        const uint32_t* _sA = qb  + (size_t)(s) * 4096; \
        const uint32_t* _sB = kvb + (size_t)(s) * 4096; \
        uint32_t* _An = &As[_j * 4096]; \
        uint32_t* _Bn = &Bs[_j * 4096]; \
        _Pragma("unroll") \
        for (int i = 0; i < 4; i++) { \
            cp16(&_An[t * 4 + i * 1024], _sA + t * 4 + i * 1024); \
            cp16(&_Bn[t * 4 + i * 1024], _sB + t * 4 + i * 1024); \
        } \
        cp_commit(); \
    } while (0)

    CTX_ISSUE(0);
    CTX_ISSUE(1);

    float acc[4][4][4] = {};
    const int KM = C_ / 32;   // 8

#pragma unroll 1
    for (int km = 0; km < KM; km++) {
        if (km < KM - 1) cp_wait<1>(); else cp_wait<0>();
        __syncthreads();
        if (km + 2 < KM) CTX_ISSUE(km + 2);

        const int cur = km % 3;
        const uint32_t* Ac = &As[cur * 4096];
        const uint32_t* Bc = &Bs[cur * 4096];
#pragma unroll
        for (int kk = 0; kk < 4; kk++) {
            uint32_t af[4][4];
            uint32_t bf[4][2];
#pragma unroll
            for (int mt = 0; mt < 4; mt++) {
                const int rt = (wid >> 2) * 4 + mt;
                const uint4 pk = *(const uint4*)&Ac[(kk * 8 + rt) * 128 + lane * 4];
                af[mt][0] = pk.x; af[mt][1] = pk.y; af[mt][2] = pk.z; af[mt][3] = pk.w;
            }
#pragma unroll
            for (int nt = 0; nt < 4; nt++) {
                const int d8t = (wid & 3) * 4 + nt;
                const uint2 pk = *(const uint2*)&Bc[(kk * 16 + d8t) * 64 + lane * 2];
                bf[nt][0] = pk.x; bf[nt][1] = pk.y;
            }
#pragma unroll
            for (int mt = 0; mt < 4; mt++)
#pragma unroll
                for (int nt = 0; nt < 4; nt++)
                    mma8(acc[mt][nt], af[mt], bf[nt]);
        }
    }

#pragma unroll
    for (int mt = 0; mt < 4; mt++)
#pragma unroll
        for (int nt = 0; nt < 4; nt++) {
            const int n = n0 + wn + mt * 16 + g;
            const int d = d0 + wd + nt * 8 + tig * 2;
            float2 v0 = make_float2(acc[mt][nt][0], acc[mt][nt][1]);
            float2 v1 = make_float2(acc[mt][nt][2], acc[mt][nt][3]);
            *(float2*)&out[((size_t)b * N_ + n) * C_ + d]       = v0;
            *(float2*)&out[((size_t)b * N_ + n + 8) * C_ + d]   = v1;
        }
}

// ---------------------------------------------------------------------------
extern "C" void kernel_launch(void* const* d_in, const int* in_sizes, int n_in,
                              void* d_out, int out_size) {
    const float* q = (const float*)d_in[0];
    const float* k = (const float*)d_in[1];
    const float* v = (const float*)d_in[2];
    float* out = (float*)d_out;

    const int smem_pq  = (64 * PSQ + 64) * 4;             // ~66.8 KB
    const int smem_kv  = (2 * 4096 + 2 * 32 * STA) * 4;   // ~67.6 KB
    const int smem_red = 256 * RST * 4;                   // 73.7 KB
    const int smem_ctx = (6 * 4096) * 4;                  // 96 KB
    cudaFuncSetAttribute(prep_q_kernel, cudaFuncAttributeMaxDynamicSharedMemorySize, smem_pq);
    cudaFuncSetAttribute(kv_kernel,     cudaFuncAttributeMaxDynamicSharedMemorySize, smem_kv);
    cudaFuncSetAttribute(reduce_kernel, cudaFuncAttributeMaxDynamicSharedMemorySize, smem_red);
    cudaFuncSetAttribute(ctx_kernel,    cudaFuncAttributeMaxDynamicSharedMemorySize, smem_ctx);

    // 1a) k row norms
    rnorm_k_kernel<<<(B_ * M_) / 8, 256>>>(k);
    // 1b) q -> packed qn (norm + 1/N folded)
    prep_q_kernel<<<dim3(N_ / 64, B_), 256, smem_pq>>>(q);
    // 2) split-K partial kv = (k*rk)^T @ v, pack fused into producer
    kv_kernel<<<dim3(C_ / 128, C_ / 128, B_ * SPLITS), 256, smem_kv>>>(k, v);
    // 2b) reduce partials -> packed tf32 kv (SMEM-staged)
    reduce_kernel<<<dim3(4, B_), 256, smem_red>>>();
    // 3) out = qn @ kv (3-stage ring)
    ctx_kernel<<<dim3(C_ / 128, N_ / 128, B_), 256, smem_ctx>>>(out);
}

// round 11
// speedup vs baseline: 1.0008x; 1.0008x over previous
#include <cuda_runtime.h>
#include <cstdint>
#include <cstddef>

#define B_ 8
#define N_ 4096
#define M_ 4096
#define C_ 256

#define SPLITS 8
#define KM_PER_SPLIT 16      // 16 * 32 = 512 m-rows per split
#define STA 136              // stride (words) for kv's raw-v [32][128] tile
#define PSQ 260              // prep q smem stride (words): 260 mod 32 = 4
#define RST 72               // reduce smem stride (words): 8*tig+g banks distinct

// Scratch (static device arrays; no allocations allowed)
// g_qn: [b][n_tile 32][km 8][kk 4][rt 8][lane 32][w 4]  packed tf32(q*rq/N)
// g_kv: [b][d_tile 2][km 8][kk 4][d8t 16][lane 32][w 2] packed tf32 kv
__device__ uint32_t g_qn[B_ * N_ * C_];
__device__ float    g_rk[B_ * M_];
__device__ float    g_kvp[SPLITS * B_ * C_ * C_];
__device__ uint32_t g_kv[B_ * C_ * C_];

__device__ __forceinline__ uint32_t f2tf(float x) {
    uint32_t r;
    asm("cvt.rna.tf32.f32 %0, %1;" : "=r"(r) : "f"(x));
    return r;
}

__device__ __forceinline__ void mma8(float c[4], const uint32_t a[4], const uint32_t b[2]) {
    asm volatile(
        "mma.sync.aligned.m16n8k8.row.col.f32.tf32.tf32.f32 "
        "{%0,%1,%2,%3}, {%4,%5,%6,%7}, {%8,%9}, {%0,%1,%2,%3};\n"
        : "+f"(c[0]), "+f"(c[1]), "+f"(c[2]), "+f"(c[3])
        : "r"(a[0]), "r"(a[1]), "r"(a[2]), "r"(a[3]),
          "r"(b[0]), "r"(b[1]));
}

__device__ __forceinline__ void cp16(void* smem, const void* gmem) {
    uint32_t s = (uint32_t)__cvta_generic_to_shared(smem);
    asm volatile("cp.async.cg.shared.global [%0], [%1], 16;\n" :: "r"(s), "l"(gmem));
}
__device__ __forceinline__ void cp_commit() { asm volatile("cp.async.commit_group;\n" ::: "memory"); }
template <int NN>
__device__ __forceinline__ void cp_wait() { asm volatile("cp.async.wait_group %0;\n" :: "n"(NN) : "memory"); }

// ---------------------------------------------------------------------------
// Kernel 1a: k row reciprocal norms (tiny output).
// ---------------------------------------------------------------------------
__global__ __launch_bounds__(256) void rnorm_k_kernel(const float* __restrict__ k) {
    const int r = (blockIdx.x * blockDim.x + threadIdx.x) >> 5;
    const int lane = threadIdx.x & 31;
    const float* src = k + (size_t)r * C_;
    float4 a = *(const float4*)(src + lane * 4);
    float4 b = *(const float4*)(src + 128 + lane * 4);
    float ss = a.x * a.x + a.y * a.y + a.z * a.z + a.w * a.w
             + b.x * b.x + b.y * b.y + b.z * b.z + b.w * b.w;
#pragma unroll
    for (int o = 16; o > 0; o >>= 1) ss += __shfl_xor_sync(0xffffffffu, ss, o);
    if (lane == 0) g_rk[r] = (ss > 1e-24f) ? rsqrtf(ss) : 1e12f;
}

// ---------------------------------------------------------------------------
// Kernel 1b: prep q -> packed A-fragments (norm and 1/N folded). Validated R6.
// ---------------------------------------------------------------------------
__global__ __launch_bounds__(256) void prep_q_kernel(const float* __restrict__ q) {
    extern __shared__ float sq[];              // [64][PSQ] + rn[64]
    float* rn = sq + 64 * PSQ;

    const int b    = blockIdx.y;
    const int row0 = blockIdx.x * 64;
    const int t = threadIdx.x, lane = t & 31, wid = t >> 5;

#pragma unroll
    for (int i = 0; i < 8; i++) {
        const int rl = wid * 8 + i;
        const float* src = q + ((size_t)b * N_ + row0 + rl) * C_;
        float4 a = *(const float4*)(src + lane * 4);
        float4 c = *(const float4*)(src + 128 + lane * 4);
        *(float4*)&sq[rl * PSQ + lane * 4]       = a;
        *(float4*)&sq[rl * PSQ + 128 + lane * 4] = c;
        float ss = a.x * a.x + a.y * a.y + a.z * a.z + a.w * a.w
                 + c.x * c.x + c.y * c.y + c.z * c.z + c.w * c.w;
#pragma unroll
        for (int o = 16; o > 0; o >>= 1) ss += __shfl_xor_sync(0xffffffffu, ss, o);
        if (lane == 0) {
            float r = (ss > 1e-24f) ? rsqrtf(ss) : 1e12f;
            rn[rl] = r * (1.0f / (float)N_);
        }
    }
    __syncthreads();

    const int n_tile = blockIdx.x >> 1;
    const int rt_hi  = (blockIdx.x & 1) * 4;
    const int g = lane >> 2, tig = lane & 3;
    uint32_t* obase = g_qn + (size_t)(b * 32 + n_tile) * 32768;

#pragma unroll 1
    for (int it = 0; it < 16; it++) {
        const int bid = it * 8 + wid;
        const int km = bid >> 4, kk = (bid >> 2) & 3, rt = bid & 3;
        const int c0 = km * 32 + kk * 8 + tig;
        const int r0 = rt * 16 + g;
        const float s0 = rn[r0], s1 = rn[r0 + 8];
        uint4 o;
        o.x = f2tf(sq[r0 * PSQ + c0] * s0);
        o.y = f2tf(sq[(r0 + 8) * PSQ + c0] * s1);
        o.z = f2tf(sq[r0 * PSQ + c0 + 4] * s0);
        o.w = f2tf(sq[(r0 + 8) * PSQ + c0 + 4] * s1);
        *(uint4*)&obase[(size_t)(((km * 4 + kk) * 8 + rt_hi + rt) * 128) + lane * 4] = o;
    }
}

// ---------------------------------------------------------------------------
// Kernel 2: split-K partials of kv (validated R7: fused A-pack from raw k).
// ---------------------------------------------------------------------------
__global__ __launch_bounds__(256, 2) void kv_kernel(const float* __restrict__ k,
                                                    const float* __restrict__ v) {
    extern __shared__ uint32_t sm[];
    uint32_t* As = sm;                        // [2][4096] packed A
    float*    Bs = (float*)(sm + 2 * 4096);   // [2][32*STA] raw fp32

    const int bz = blockIdx.z;
    const int b  = bz >> 3;
    const int sp = bz & 7;
    const int c0 = blockIdx.y * 128;
    const int d0 = blockIdx.x * 128;
    const int m_base = sp * (KM_PER_SPLIT * 32);

    const int t = threadIdx.x, lane = t & 31, wid = t >> 5;
    const int g = lane >> 2, tig = lane & 3;
    const int wc = (wid >> 2) * 64;
    const int wd = (wid & 3) * 32;
    const int lr = t >> 3;
    const int lq = (t & 7) * 4;

    const float* kb  = k + (size_t)b * M_ * C_;
    const float* vb  = v + (size_t)b * M_ * C_ + d0;
    const float* rkb = g_rk + b * M_;

    int kkA[4], ctA[4];
#pragma unroll
    for (int i = 0; i < 4; i++) { const int bid = wid * 4 + i; kkA[i] = bid >> 3; ctA[i] = bid & 7; }

    float pv[4][4];
    float pr[4][2];

#define KV_LOAD_A(m0) do { \
    _Pragma("unroll") \
    for (int i = 0; i < 4; i++) { \
        const int mr = (m0) + kkA[i] * 8 + tig; \
        const int cc = c0 + ctA[i] * 16 + g; \
        pv[i][0] = kb[(size_t)mr * C_ + cc]; \
        pv[i][1] = kb[(size_t)mr * C_ + cc + 8]; \
        pv[i][2] = kb[(size_t)(mr + 4) * C_ + cc]; \
        pv[i][3] = kb[(size_t)(mr + 4) * C_ + cc + 8]; \
        pr[i][0] = __ldg(rkb + mr); \
        pr[i][1] = __ldg(rkb + mr + 4); \
    } \
} while (0)

#define KV_STS_A(dst) do { \
    _Pragma("unroll") \
    for (int i = 0; i < 4; i++) { \
        uint4 o; \
        o.x = f2tf(pv[i][0] * pr[i][0]); \
        o.y = f2tf(pv[i][1] * pr[i][0]); \
        o.z = f2tf(pv[i][2] * pr[i][1]); \
        o.w = f2tf(pv[i][3] * pr[i][1]); \
        *(uint4*)&(dst)[(kkA[i] * 8 + ctA[i]) * 128 + lane * 4] = o; \
    } \
} while (0)

    KV_LOAD_A(m_base);
    KV_STS_A(As);
#pragma unroll
    for (int i = 0; i < 4; i++)
        cp16(&Bs[lr * STA + lq + i * 32], vb + (size_t)(m_base + lr) * C_ + lq + i * 32);
    cp_commit();
    KV_LOAD_A(m_base + 32);

    float acc[4][4][4] = {};

#pragma unroll 1
    for (int km = 0; km < KM_PER_SPLIT; km++) {
        const int cur = km & 1;
        const int nxt = cur ^ 1;
        if (km + 1 < KM_PER_SPLIT) {
            const int m0 = m_base + (km + 1) * 32;
            float* Bn = &Bs[nxt * 32 * STA];
#pragma unroll
            for (int i = 0; i < 4; i++)
                cp16(&Bn[lr * STA + lq + i * 32], vb + (size_t)(m0 + lr) * C_ + lq + i * 32);
            cp_commit();
            cp_wait<1>();
        } else {
            cp_wait<0>();
        }
        __syncthreads();

        const uint32_t* Ac = &As[cur * 4096];
        const float*    Bc = &Bs[cur * 32 * STA];
#pragma unroll
        for (int kk = 0; kk < 4; kk++) {
            const int k8 = kk * 8;
            uint32_t af[4][4];
            uint32_t bf[4][2];
#pragma unroll
            for (int mt = 0; mt < 4; mt++) {
                const int rt = (wid >> 2) * 4 + mt;
                const uint4 pk = *(const uint4*)&Ac[(kk * 8 + rt) * 128 + lane * 4];
                af[mt][0] = pk.x; af[mt][1] = pk.y; af[mt][2] = pk.z; af[mt][3] = pk.w;
            }
#pragma unroll
            for (int nt = 0; nt < 4; nt++) {
                const int col = wd + nt * 8 + g;
                bf[nt][0] = f2tf(Bc[(k8 + tig) * STA + col]);
                bf[nt][1] = f2tf(Bc[(k8 + tig + 4) * STA + col]);
            }
#pragma unroll
            for (int mt = 0; mt < 4; mt++)
#pragma unroll
                for (int nt = 0; nt < 4; nt++)
                    mma8(acc[mt][nt], af[mt], bf[nt]);
        }

        if (km + 1 < KM_PER_SPLIT) {
            KV_STS_A(&As[nxt * 4096]);
            if (km + 2 < KM_PER_SPLIT) KV_LOAD_A(m_base + (km + 2) * 32);
        }
        __syncthreads();
    }

    float* kvp = g_kvp + ((size_t)sp * B_ + b) * C_ * C_;
#pragma unroll
    for (int mt = 0; mt < 4; mt++)
#pragma unroll
        for (int nt = 0; nt < 4; nt++) {
            const int c = c0 + wc + mt * 16 + g;
            const int d = d0 + wd + nt * 8 + tig * 2;
            float2 v0 = make_float2(acc[mt][nt][0], acc[mt][nt][1]);
            float2 v1 = make_float2(acc[mt][nt][2], acc[mt][nt][3]);
            *(float2*)&kvp[(size_t)c * C_ + d]       = v0;
            *(float2*)&kvp[(size_t)(c + 8) * C_ + d] = v1;
        }
}

// ---------------------------------------------------------------------------
// Kernel 2b: reduce partials -> packed tf32 B-frags, SMEM-staged.
// CTA per (d-64-block, b). Phase 1: coalesced float4 accumulate into
// [256c][64d] tile (stride RST=72). Phase 2: conflict-free packed emit.
// ---------------------------------------------------------------------------
__global__ __launch_bounds__(256) void reduce_kernel() {
    extern __shared__ float rsm[];             // [256][RST]
    const int dq = blockIdx.x;                 // 0..3 (64-d block)
    const int b  = blockIdx.y;
    const int t = threadIdx.x, lane = t & 31, wid = t >> 5;

    // phase 1: accumulate
#pragma unroll 1
    for (int p = 0; p < 16; p++) {
        const int idx = p * 256 + t;
        const int c   = idx >> 4;
        const int dl4 = (idx & 15) * 4;
        float4 a = make_float4(0.f, 0.f, 0.f, 0.f);
#pragma unroll
        for (int sp = 0; sp < SPLITS; sp++) {
            const float4 x = *(const float4*)&g_kvp[((size_t)(sp * B_ + b) << 16)
                                                    + (size_t)c * C_ + dq * 64 + dl4];
            a.x += x.x; a.y += x.y; a.z += x.z; a.w += x.w;
        }
        *(float4*)&rsm[c * RST + dl4] = a;
    }
    __syncthreads();

    // phase 2: emit packed (dt = dq>>1, d8t = (dq&1)*8 + wid)
    const int g = lane >> 2, tig = lane & 3;
    const int dt  = dq >> 1;
    const int d8t = (dq & 1) * 8 + wid;
    const int dl  = wid * 8 + g;
#pragma unroll
    for (int km = 0; km < 8; km++)
#pragma unroll
        for (int kk = 0; kk < 4; kk++) {
            const int c = km * 32 + kk * 8 + tig;
            uint2 o;
            o.x = f2tf(rsm[c * RST + dl]);
            o.y = f2tf(rsm[(c + 4) * RST + dl]);
            const int idx = (b << 15) | (dt << 14) | (km << 11) | (kk << 9)
                          | (d8t << 5) | lane;
            *(uint2*)&g_kv[(size_t)idx * 2] = o;
        }
}

// ---------------------------------------------------------------------------
// Kernel 3: ctx GEMM, packed operands, 3-stage cp.async ring, ONE sync/iter.
// Order per iter: wait -> sync -> issue(s+2) -> MMA(s). Buffer (s+2)%3 was
// consumed at iter s-1, before this iter's sync -> overwrite-safe.
// ---------------------------------------------------------------------------
__global__ __launch_bounds__(256, 2) void ctx_kernel(float* __restrict__ out) {
    extern __shared__ uint32_t sm[];
    uint32_t* As = sm;              // [3][4096]
    uint32_t* Bs = sm + 3 * 4096;   // [3][4096]

    const int b  = blockIdx.z;
    const int n_tile = blockIdx.y;
    const int dt = blockIdx.x;
    const int n0 = n_tile * 128;
    const int d0 = dt * 128;

    const int t = threadIdx.x, lane = t & 31, wid = t >> 5;
    const int g = lane >> 2, tig = lane & 3;
    const int wn = (wid >> 2) * 64;
    const int wd = (wid & 3) * 32;

    const uint32_t* qb  = g_qn + (size_t)(b * 32 + n_tile) * 32768;
    const uint32_t* kvb = g_kv + (size_t)(b * 2 + dt) * 32768;

#define CTX_ISSUE(s) do { \
        const int _j = (s) % 3; \
        const uint32_t* _sA = qb  + (size_t)(s) * 4096; \
        const uint32_t* _sB = kvb + (size_t)(s) * 4096; \
        uint32_t* _An = &As[_j * 4096]; \
        uint32_t* _Bn = &Bs[_j * 4096]; \
        _Pragma("unroll") \
        for (int i = 0; i < 4; i++) { \
            cp16(&_An[t * 4 + i * 1024], _sA + t * 4 + i * 1024); \
            cp16(&_Bn[t * 4 + i * 1024], _sB + t * 4 + i * 1024); \
        } \
        cp_commit(); \
    } while (0)

    CTX_ISSUE(0);
    CTX_ISSUE(1);

    float acc[4][4][4] = {};
    const int KM = C_ / 32;   // 8

#pragma unroll 1
    for (int km = 0; km < KM; km++) {
        if (km < KM - 1) cp_wait<1>(); else cp_wait<0>();
        __syncthreads();
        if (km + 2 < KM) CTX_ISSUE(km + 2);

        const int cur = km % 3;
        const uint32_t* Ac = &As[cur * 4096];
        const uint32_t* Bc = &Bs[cur * 4096];
#pragma unroll
        for (int kk = 0; kk < 4; kk++) {
            uint32_t af[4][4];
            uint32_t bf[4][2];
#pragma unroll
            for (int mt = 0; mt < 4; mt++) {
                const int rt = (wid >> 2) * 4 + mt;
                const uint4 pk = *(const uint4*)&Ac[(kk * 8 + rt) * 128 + lane * 4];
                af[mt][0] = pk.x; af[mt][1] = pk.y; af[mt][2] = pk.z; af[mt][3] = pk.w;
            }
#pragma unroll
            for (int nt = 0; nt < 4; nt++) {
                const int d8t = (wid & 3) * 4 + nt;
                const uint2 pk = *(const uint2*)&Bc[(kk * 16 + d8t) * 64 + lane * 2];
                bf[nt][0] = pk.x; bf[nt][1] = pk.y;
            }
#pragma unroll
            for (int mt = 0; mt < 4; mt++)
#pragma unroll
                for (int nt = 0; nt < 4; nt++)
                    mma8(acc[mt][nt], af[mt], bf[nt]);
        }
    }

#pragma unroll
    for (int mt = 0; mt < 4; mt++)
#pragma unroll
        for (int nt = 0; nt < 4; nt++) {
            const int n = n0 + wn + mt * 16 + g;
            const int d = d0 + wd + nt * 8 + tig * 2;
            float2 v0 = make_float2(acc[mt][nt][0], acc[mt][nt][1]);
            float2 v1 = make_float2(acc[mt][nt][2], acc[mt][nt][3]);
            *(float2*)&out[((size_t)b * N_ + n) * C_ + d]       = v0;
            *(float2*)&out[((size_t)b * N_ + n + 8) * C_ + d]   = v1;
        }
}

// ---------------------------------------------------------------------------
extern "C" void kernel_launch(void* const* d_in, const int* in_sizes, int n_in,
                              void* d_out, int out_size) {
    const float* q = (const float*)d_in[0];
    const float* k = (const float*)d_in[1];
    const float* v = (const float*)d_in[2];
    float* out = (float*)d_out;

    const int smem_pq  = (64 * PSQ + 64) * 4;             // ~66.8 KB
    const int smem_kv  = (2 * 4096 + 2 * 32 * STA) * 4;   // ~67.6 KB
    const int smem_red = 256 * RST * 4;                   // 73.7 KB
    const int smem_ctx = (6 * 4096) * 4;                  // 96 KB
    cudaFuncSetAttribute(prep_q_kernel, cudaFuncAttributeMaxDynamicSharedMemorySize, smem_pq);
    cudaFuncSetAttribute(kv_kernel,     cudaFuncAttributeMaxDynamicSharedMemorySize, smem_kv);
    cudaFuncSetAttribute(reduce_kernel, cudaFuncAttributeMaxDynamicSharedMemorySize, smem_red);
    cudaFuncSetAttribute(ctx_kernel,    cudaFuncAttributeMaxDynamicSharedMemorySize, smem_ctx);

    // 1a) k row norms
    rnorm_k_kernel<<<(B_ * M_) / 8, 256>>>(k);
    // 1b) q -> packed qn (norm + 1/N folded)
    prep_q_kernel<<<dim3(N_ / 64, B_), 256, smem_pq>>>(q);
    // 2) split-K partial kv = (k*rk)^T @ v, pack fused into producer
    kv_kernel<<<dim3(C_ / 128, C_ / 128, B_ * SPLITS), 256, smem_kv>>>(k, v);
    // 2b) reduce partials -> packed tf32 kv (SMEM-staged)
    reduce_kernel<<<dim3(4, B_), 256, smem_red>>>();
    // 3) out = qn @ kv (3-stage ring)
    ctx_kernel<<<dim3(C_ / 128, N_ / 128, B_), 256, smem_ctx>>>(out);
}

// round 12
// speedup vs baseline: 1.1536x; 1.1526x over previous
#include <cuda_runtime.h>
#include <cstdint>
#include <cstddef>

#define B_ 8
#define N_ 4096
#define M_ 4096
#define C_ 256

#define SPLITS 8
#define KM_PER_SPLIT 16      // 16 * 32 = 512 m-rows per split
#define STA 136              // stride (words) for kv's raw-v [32][128] tile
#define PSQ 260              // prep q smem stride (words): 260 mod 32 = 4
#define RST 72               // reduce smem stride (words): 8*tig+g banks distinct

// Scratch (static device arrays; no allocations allowed)
// g_qn: [b][n_tile 32][km 8][kk 4][rt 8][lane 32][w 4]  packed tf32(q*rq/N)
// g_kv: [b][d_tile 2][km 8][kk 4][d8t 16][lane 32][w 2] packed tf32 kv
__device__ uint32_t g_qn[B_ * N_ * C_];
__device__ float    g_rk[B_ * M_];
__device__ float    g_kvp[SPLITS * B_ * C_ * C_];
__device__ uint32_t g_kv[B_ * C_ * C_];

__device__ __forceinline__ uint32_t f2tf(float x) {
    uint32_t r;
    asm("cvt.rna.tf32.f32 %0, %1;" : "=r"(r) : "f"(x));
    return r;
}

__device__ __forceinline__ void mma8(float c[4], const uint32_t a[4], const uint32_t b[2]) {
    asm volatile(
        "mma.sync.aligned.m16n8k8.row.col.f32.tf32.tf32.f32 "
        "{%0,%1,%2,%3}, {%4,%5,%6,%7}, {%8,%9}, {%0,%1,%2,%3};\n"
        : "+f"(c[0]), "+f"(c[1]), "+f"(c[2]), "+f"(c[3])
        : "r"(a[0]), "r"(a[1]), "r"(a[2]), "r"(a[3]),
          "r"(b[0]), "r"(b[1]));
}

__device__ __forceinline__ void cp16(void* smem, const void* gmem) {
    uint32_t s = (uint32_t)__cvta_generic_to_shared(smem);
    asm volatile("cp.async.cg.shared.global [%0], [%1], 16;\n" :: "r"(s), "l"(gmem));
}
__device__ __forceinline__ void cp_commit() { asm volatile("cp.async.commit_group;\n" ::: "memory"); }
template <int NN>
__device__ __forceinline__ void cp_wait() { asm volatile("cp.async.wait_group %0;\n" :: "n"(NN) : "memory"); }

// ---------------------------------------------------------------------------
// Kernel 1 (fused prep): 1D grid.
//   CTA x <  512 : prep_q block (rowblock = x & 63, b = x >> 6) — R6-validated
//   CTA x >= 512 : k row norms (8 warps, one row each)
// ---------------------------------------------------------------------------
#define PREPQ_CTAS 512

__global__ __launch_bounds__(256) void prep_kernel(const float* __restrict__ q,
                                                   const float* __restrict__ k) {
    const int t = threadIdx.x, lane = t & 31, wid = t >> 5;

    if (blockIdx.x >= PREPQ_CTAS) {
        // ---- k norms ----
        const int r = (((int)blockIdx.x - PREPQ_CTAS) * 256 + t) >> 5;
        const float* src = k + (size_t)r * C_;
        float4 a = *(const float4*)(src + lane * 4);
        float4 b = *(const float4*)(src + 128 + lane * 4);
        float ss = a.x * a.x + a.y * a.y + a.z * a.z + a.w * a.w
                 + b.x * b.x + b.y * b.y + b.z * b.z + b.w * b.w;
#pragma unroll
        for (int o = 16; o > 0; o >>= 1) ss += __shfl_xor_sync(0xffffffffu, ss, o);
        if (lane == 0) g_rk[r] = (ss > 1e-24f) ? rsqrtf(ss) : 1e12f;
        return;
    }

    // ---- prep_q ----
    extern __shared__ float sq[];              // [64][PSQ] + rn[64]
    float* rn = sq + 64 * PSQ;

    const int xb   = blockIdx.x;               // 0..511
    const int b    = xb >> 6;
    const int rowblock = xb & 63;
    const int row0 = rowblock * 64;

#pragma unroll
    for (int i = 0; i < 8; i++) {
        const int rl = wid * 8 + i;
        const float* src = q + ((size_t)b * N_ + row0 + rl) * C_;
        float4 a = *(const float4*)(src + lane * 4);
        float4 c = *(const float4*)(src + 128 + lane * 4);
        *(float4*)&sq[rl * PSQ + lane * 4]       = a;
        *(float4*)&sq[rl * PSQ + 128 + lane * 4] = c;
        float ss = a.x * a.x + a.y * a.y + a.z * a.z + a.w * a.w
                 + c.x * c.x + c.y * c.y + c.z * c.z + c.w * c.w;
#pragma unroll
        for (int o = 16; o > 0; o >>= 1) ss += __shfl_xor_sync(0xffffffffu, ss, o);
        if (lane == 0) {
            float r = (ss > 1e-24f) ? rsqrtf(ss) : 1e12f;
            rn[rl] = r * (1.0f / (float)N_);
        }
    }
    __syncthreads();

    const int n_tile = rowblock >> 1;
    const int rt_hi  = (rowblock & 1) * 4;
    const int g = lane >> 2, tig = lane & 3;
    uint32_t* obase = g_qn + (size_t)(b * 32 + n_tile) * 32768;

#pragma unroll 1
    for (int it = 0; it < 16; it++) {
        const int bid = it * 8 + wid;
        const int km = bid >> 4, kk = (bid >> 2) & 3, rt = bid & 3;
        const int c0 = km * 32 + kk * 8 + tig;
        const int r0 = rt * 16 + g;
        const float s0 = rn[r0], s1 = rn[r0 + 8];
        uint4 o;
        o.x = f2tf(sq[r0 * PSQ + c0] * s0);
        o.y = f2tf(sq[(r0 + 8) * PSQ + c0] * s1);
        o.z = f2tf(sq[r0 * PSQ + c0 + 4] * s0);
        o.w = f2tf(sq[(r0 + 8) * PSQ + c0 + 4] * s1);
        *(uint4*)&obase[(size_t)(((km * 4 + kk) * 8 + rt_hi + rt) * 128) + lane * 4] = o;
    }
}

// ---------------------------------------------------------------------------
// Kernel 2: split-K partials of kv (validated R7/R11: fused A-pack from raw k).
// ---------------------------------------------------------------------------
__global__ __launch_bounds__(256, 2) void kv_kernel(const float* __restrict__ k,
                                                    const float* __restrict__ v) {
    extern __shared__ uint32_t sm[];
    uint32_t* As = sm;                        // [2][4096] packed A
    float*    Bs = (float*)(sm + 2 * 4096);   // [2][32*STA] raw fp32

    const int bz = blockIdx.z;
    const int b  = bz >> 3;
    const int sp = bz & 7;
    const int c0 = blockIdx.y * 128;
    const int d0 = blockIdx.x * 128;
    const int m_base = sp * (KM_PER_SPLIT * 32);

    const int t = threadIdx.x, lane = t & 31, wid = t >> 5;
    const int g = lane >> 2, tig = lane & 3;
    const int wc = (wid >> 2) * 64;
    const int wd = (wid & 3) * 32;
    const int lr = t >> 3;
    const int lq = (t & 7) * 4;

    const float* kb  = k + (size_t)b * M_ * C_;
    const float* vb  = v + (size_t)b * M_ * C_ + d0;
    const float* rkb = g_rk + b * M_;

    int kkA[4], ctA[4];
#pragma unroll
    for (int i = 0; i < 4; i++) { const int bid = wid * 4 + i; kkA[i] = bid >> 3; ctA[i] = bid & 7; }

    float pv[4][4];
    float pr[4][2];

#define KV_LOAD_A(m0) do { \
    _Pragma("unroll") \
    for (int i = 0; i < 4; i++) { \
        const int mr = (m0) + kkA[i] * 8 + tig; \
        const int cc = c0 + ctA[i] * 16 + g; \
        pv[i][0] = kb[(size_t)mr * C_ + cc]; \
        pv[i][1] = kb[(size_t)mr * C_ + cc + 8]; \
        pv[i][2] = kb[(size_t)(mr + 4) * C_ + cc]; \
        pv[i][3] = kb[(size_t)(mr + 4) * C_ + cc + 8]; \
        pr[i][0] = __ldg(rkb + mr); \
        pr[i][1] = __ldg(rkb + mr + 4); \
    } \
} while (0)

#define KV_STS_A(dst) do { \
    _Pragma("unroll") \
    for (int i = 0; i < 4; i++) { \
        uint4 o; \
        o.x = f2tf(pv[i][0] * pr[i][0]); \
        o.y = f2tf(pv[i][1] * pr[i][0]); \
        o.z = f2tf(pv[i][2] * pr[i][1]); \
        o.w = f2tf(pv[i][3] * pr[i][1]); \
        *(uint4*)&(dst)[(kkA[i] * 8 + ctA[i]) * 128 + lane * 4] = o; \
    } \
} while (0)

    KV_LOAD_A(m_base);
    KV_STS_A(As);
#pragma unroll
    for (int i = 0; i < 4; i++)
        cp16(&Bs[lr * STA + lq + i * 32], vb + (size_t)(m_base + lr) * C_ + lq + i * 32);
    cp_commit();
    KV_LOAD_A(m_base + 32);

    float acc[4][4][4] = {};

#pragma unroll 1
    for (int km = 0; km < KM_PER_SPLIT; km++) {
        const int cur = km & 1;
        const int nxt = cur ^ 1;
        if (km + 1 < KM_PER_SPLIT) {
            const int m0 = m_base + (km + 1) * 32;
            float* Bn = &Bs[nxt * 32 * STA];
#pragma unroll
            for (int i = 0; i < 4; i++)
                cp16(&Bn[lr * STA + lq + i * 32], vb + (size_t)(m0 + lr) * C_ + lq + i * 32);
            cp_commit();
            cp_wait<1>();
        } else {
            cp_wait<0>();
        }
        __syncthreads();

        const uint32_t* Ac = &As[cur * 4096];
        const float*    Bc = &Bs[cur * 32 * STA];
#pragma unroll
        for (int kk = 0; kk < 4; kk++) {
            const int k8 = kk * 8;
            uint32_t af[4][4];
            uint32_t bf[4][2];
#pragma unroll
            for (int mt = 0; mt < 4; mt++) {
                const int rt = (wid >> 2) * 4 + mt;
                const uint4 pk = *(const uint4*)&Ac[(kk * 8 + rt) * 128 + lane * 4];
                af[mt][0] = pk.x; af[mt][1] = pk.y; af[mt][2] = pk.z; af[mt][3] = pk.w;
            }
#pragma unroll
            for (int nt = 0; nt < 4; nt++) {
                const int col = wd + nt * 8 + g;
                bf[nt][0] = f2tf(Bc[(k8 + tig) * STA + col]);
                bf[nt][1] = f2tf(Bc[(k8 + tig + 4) * STA + col]);
            }
#pragma unroll
            for (int mt = 0; mt < 4; mt++)
#pragma unroll
                for (int nt = 0; nt < 4; nt++)
                    mma8(acc[mt][nt], af[mt], bf[nt]);
        }

        if (km + 1 < KM_PER_SPLIT) {
            KV_STS_A(&As[nxt * 4096]);
            if (km + 2 < KM_PER_SPLIT) KV_LOAD_A(m_base + (km + 2) * 32);
        }
        __syncthreads();
    }

    float* kvp = g_kvp + ((size_t)sp * B_ + b) * C_ * C_;
#pragma unroll
    for (int mt = 0; mt < 4; mt++)
#pragma unroll
        for (int nt = 0; nt < 4; nt++) {
            const int c = c0 + wc + mt * 16 + g;
            const int d = d0 + wd + nt * 8 + tig * 2;
            float2 v0 = make_float2(acc[mt][nt][0], acc[mt][nt][1]);
            float2 v1 = make_float2(acc[mt][nt][2], acc[mt][nt][3]);
            *(float2*)&kvp[(size_t)c * C_ + d]       = v0;
            *(float2*)&kvp[(size_t)(c + 8) * C_ + d] = v1;
        }
}

// ---------------------------------------------------------------------------
// Kernel 2b: reduce partials -> packed tf32 B-frags.
// Grid (dq 4, km 8, b 8) = 256 CTAs; CTA owns a 32c x 64d tile.
// Phase 1: register-accumulate coalesced float4 over splits -> SMEM [32][RST].
// Phase 2: conflict-free packed emit (banks 8*tig+g distinct; 256B runs).
// ---------------------------------------------------------------------------
__global__ __launch_bounds__(256) void reduce_kernel() {
    __shared__ float rsm[32 * RST];
    const int dq = blockIdx.x;                 // 0..3 (64-d block)
    const int km = blockIdx.y;                 // 0..7 (32-c block)
    const int b  = blockIdx.z;
    const int t = threadIdx.x, lane = t & 31, wid = t >> 5;

    // phase 1: accumulate 2 float4 per thread
#pragma unroll
    for (int p = 0; p < 2; p++) {
        const int idx = p * 256 + t;
        const int cl  = idx >> 4;              // 0..31
        const int dl4 = (idx & 15) * 4;        // 0..60
        float4 a = make_float4(0.f, 0.f, 0.f, 0.f);
#pragma unroll
        for (int sp = 0; sp < SPLITS; sp++) {
            const float4 x = *(const float4*)&g_kvp[((size_t)(sp * B_ + b) << 16)
                                                    + (size_t)(km * 32 + cl) * C_ + dq * 64 + dl4];
            a.x += x.x; a.y += x.y; a.z += x.z; a.w += x.w;
        }
        *(float4*)&rsm[cl * RST + dl4] = a;
    }
    __syncthreads();

    // phase 2: emit 4 packed uint2 per thread
    const int g = lane >> 2, tig = lane & 3;
    const int dt = dq >> 1;
#pragma unroll
    for (int j = 0; j < 4; j++) {
        const int combo = wid * 4 + j;         // 0..31
        const int kk    = combo & 3;
        const int d8tl  = combo >> 2;          // 0..7
        const int d8t   = (dq & 1) * 8 + d8tl;
        const int cl    = kk * 8 + tig;
        const int dl    = d8tl * 8 + g;
        uint2 o;
        o.x = f2tf(rsm[cl * RST + dl]);
        o.y = f2tf(rsm[(cl + 4) * RST + dl]);
        const int idx = (b << 15) | (dt << 14) | (km << 11) | (kk << 9)
                      | (d8t << 5) | lane;
        *(uint2*)&g_kv[(size_t)idx * 2] = o;
    }
}

// ---------------------------------------------------------------------------
// Kernel 3: ctx GEMM (R11-passing: packed operands, 3-stage ring, 1 sync/iter).
// ---------------------------------------------------------------------------
__global__ __launch_bounds__(256, 2) void ctx_kernel(float* __restrict__ out) {
    extern __shared__ uint32_t sm[];
    uint32_t* As = sm;              // [3][4096]
    uint32_t* Bs = sm + 3 * 4096;   // [3][4096]

    const int b  = blockIdx.z;
    const int n_tile = blockIdx.y;
    const int dt = blockIdx.x;
    const int n0 = n_tile * 128;
    const int d0 = dt * 128;

    const int t = threadIdx.x, lane = t & 31, wid = t >> 5;
    const int g = lane >> 2, tig = lane & 3;
    const int wn = (wid >> 2) * 64;
    const int wd = (wid & 3) * 32;

    const uint32_t* qb  = g_qn + (size_t)(b * 32 + n_tile) * 32768;
    const uint32_t* kvb = g_kv + (size_t)(b * 2 + dt) * 32768;

#define CTX_ISSUE(s) do { \
        const int _j = (s) % 3; \
        const uint32_t* _sA = qb  + (size_t)(s) * 4096; \
        const uint32_t* _sB = kvb + (size_t)(s) * 4096; \
        uint32_t* _An = &As[_j * 4096]; \
        uint32_t* _Bn = &Bs[_j * 4096]; \
        _Pragma("unroll") \
        for (int i = 0; i < 4; i++) { \
            cp16(&_An[t * 4 + i * 1024], _sA + t * 4 + i * 1024); \
            cp16(&_Bn[t * 4 + i * 1024], _sB + t * 4 + i * 1024); \
        } \
        cp_commit(); \
    } while (0)

    CTX_ISSUE(0);
    CTX_ISSUE(1);

    float acc[4][4][4] = {};
    const int KM = C_ / 32;   // 8

#pragma unroll 1
    for (int km = 0; km < KM; km++) {
        if (km < KM - 1) cp_wait<1>(); else cp_wait<0>();
        __syncthreads();
        if (km + 2 < KM) CTX_ISSUE(km + 2);

        const int cur = km % 3;
        const uint32_t* Ac = &As[cur * 4096];
        const uint32_t* Bc = &Bs[cur * 4096];
#pragma unroll
        for (int kk = 0; kk < 4; kk++) {
            uint32_t af[4][4];
            uint32_t bf[4][2];
#pragma unroll
            for (int mt = 0; mt < 4; mt++) {
                const int rt = (wid >> 2) * 4 + mt;
                const uint4 pk = *(const uint4*)&Ac[(kk * 8 + rt) * 128 + lane * 4];
                af[mt][0] = pk.x; af[mt][1] = pk.y; af[mt][2] = pk.z; af[mt][3] = pk.w;
            }
#pragma unroll
            for (int nt = 0; nt < 4; nt++) {
                const int d8t = (wid & 3) * 4 + nt;
                const uint2 pk = *(const uint2*)&Bc[(kk * 16 + d8t) * 64 + lane * 2];
                bf[nt][0] = pk.x; bf[nt][1] = pk.y;
            }
#pragma unroll
            for (int mt = 0; mt < 4; mt++)
#pragma unroll
                for (int nt = 0; nt < 4; nt++)
                    mma8(acc[mt][nt], af[mt], bf[nt]);
        }
    }

#pragma unroll
    for (int mt = 0; mt < 4; mt++)
#pragma unroll
        for (int nt = 0; nt < 4; nt++) {
            const int n = n0 + wn + mt * 16 + g;
            const int d = d0 + wd + nt * 8 + tig * 2;
            float2 v0 = make_float2(acc[mt][nt][0], acc[mt][nt][1]);
            float2 v1 = make_float2(acc[mt][nt][2], acc[mt][nt][3]);
            *(float2*)&out[((size_t)b * N_ + n) * C_ + d]       = v0;
            *(float2*)&out[((size_t)b * N_ + n + 8) * C_ + d]   = v1;
        }
}

// ---------------------------------------------------------------------------
extern "C" void kernel_launch(void* const* d_in, const int* in_sizes, int n_in,
                              void* d_out, int out_size) {
    const float* q = (const float*)d_in[0];
    const float* k = (const float*)d_in[1];
    const float* v = (const float*)d_in[2];
    float* out = (float*)d_out;

    const int smem_pq  = (64 * PSQ + 64) * 4;             // ~66.8 KB
    const int smem_kv  = (2 * 4096 + 2 * 32 * STA) * 4;   // ~67.6 KB
    const int smem_ctx = (6 * 4096) * 4;                  // 96 KB
    cudaFuncSetAttribute(prep_kernel, cudaFuncAttributeMaxDynamicSharedMemorySize, smem_pq);
    cudaFuncSetAttribute(kv_kernel,   cudaFuncAttributeMaxDynamicSharedMemorySize, smem_kv);
    cudaFuncSetAttribute(ctx_kernel,  cudaFuncAttributeMaxDynamicSharedMemorySize, smem_ctx);

    // 1) fused: q -> packed qn (norm + 1/N folded) AND k row norms
    prep_kernel<<<PREPQ_CTAS + (B_ * M_) / 8, 256, smem_pq>>>(q, k);
    // 2) split-K partial kv = (k*rk)^T @ v, pack fused into producer
    kv_kernel<<<dim3(C_ / 128, C_ / 128, B_ * SPLITS), 256, smem_kv>>>(k, v);
    // 2b) reduce partials -> packed tf32 kv (256 CTAs, coalesced)
    reduce_kernel<<<dim3(4, 8, B_), 256>>>();
    // 3) out = qn @ kv (3-stage ring)
    ctx_kernel<<<dim3(C_ / 128, N_ / 128, B_), 256, smem_ctx>>>(out);
}

// round 15
// speedup vs baseline: 1.2953x; 1.1229x over previous
#include <cuda_runtime.h>
#include <cstdint>
#include <cstddef>

#define B_ 8
#define N_ 4096
#define M_ 4096
#define C_ 256

#define SPLITS 8
#define KM_PER_SPLIT 16      // 16 * 32 = 512 m-rows per split
#define STA 136              // stride (words) for kv's raw-v [32][128] tile
#define PSQ 260              // prep q smem stride (words): 260 mod 32 = 4
#define RST 72               // reduce smem stride (words)

#define KV_CTAS 256          // kv GEMM blocks in the fused kernel

// Scratch (static device arrays; no allocations allowed)
// g_qn: [b][n_tile 32][km 8][kk 4][rt 8][lane 32][w 4]  packed tf32(q*rq/N)
// g_kv: [b][d_tile 2][km 8][kk 4][d8t 16][lane 32][w 2] packed tf32 kv
__device__ uint32_t g_qn[B_ * N_ * C_];
__device__ float    g_rk[B_ * M_];
__device__ float    g_kvp[SPLITS * B_ * C_ * C_];
__device__ uint32_t g_kv[B_ * C_ * C_];

__device__ __forceinline__ uint32_t f2tf(float x) {
    uint32_t r;
    asm("cvt.rna.tf32.f32 %0, %1;" : "=r"(r) : "f"(x));
    return r;
}

__device__ __forceinline__ void mma8(float c[4], const uint32_t a[4], const uint32_t b[2]) {
    asm volatile(
        "mma.sync.aligned.m16n8k8.row.col.f32.tf32.tf32.f32 "
        "{%0,%1,%2,%3}, {%4,%5,%6,%7}, {%8,%9}, {%0,%1,%2,%3};\n"
        : "+f"(c[0]), "+f"(c[1]), "+f"(c[2]), "+f"(c[3])
        : "r"(a[0]), "r"(a[1]), "r"(a[2]), "r"(a[3]),
          "r"(b[0]), "r"(b[1]));
}

__device__ __forceinline__ void cp16(void* smem, const void* gmem) {
    uint32_t s = (uint32_t)__cvta_generic_to_shared(smem);
    asm volatile("cp.async.cg.shared.global [%0], [%1], 16;\n" :: "r"(s), "l"(gmem));
}
__device__ __forceinline__ void cp_commit() { asm volatile("cp.async.commit_group;\n" ::: "memory"); }
template <int NN>
__device__ __forceinline__ void cp_wait() { asm volatile("cp.async.wait_group %0;\n" :: "n"(NN) : "memory"); }

// ---------------------------------------------------------------------------
// Kernel 1: k row reciprocal norms (must precede kv).
// ---------------------------------------------------------------------------
__global__ __launch_bounds__(256) void knorm_kernel(const float* __restrict__ k) {
    const int r = (blockIdx.x * blockDim.x + threadIdx.x) >> 5;
    const int lane = threadIdx.x & 31;
    const float* src = k + (size_t)r * C_;
    float4 a = *(const float4*)(src + lane * 4);
    float4 b = *(const float4*)(src + 128 + lane * 4);
    float ss = a.x * a.x + a.y * a.y + a.z * a.z + a.w * a.w
             + b.x * b.x + b.y * b.y + b.z * b.z + b.w * b.w;
#pragma unroll
    for (int o = 16; o > 0; o >>= 1) ss += __shfl_xor_sync(0xffffffffu, ss, o);
    if (lane == 0) g_rk[r] = (ss > 1e-24f) ? rsqrtf(ss) : 1e12f;
}

// ---------------------------------------------------------------------------
// Kernel 2 (fused): CTAs [0, 256): kv split-K GEMM (R7/R11-validated body).
//                   CTAs [256, 768): q-pack (R6/R12-validated body).
// Both DRAM-bound halves co-resident -> overlapped on the memory system.
// ---------------------------------------------------------------------------
__global__ __launch_bounds__(256, 2) void kvq_kernel(const float* __restrict__ k,
                                                     const float* __restrict__ v,
                                                     const float* __restrict__ q) {
    extern __shared__ uint32_t sm[];
    const int t = threadIdx.x, lane = t & 31, wid = t >> 5;
    const int g = lane >> 2, tig = lane & 3;

    if (blockIdx.x >= KV_CTAS) {
        // ================= q-pack path =================
        float* sq = (float*)sm;                // [64][PSQ] + rn[64]
        float* rn = sq + 64 * PSQ;

        const int xb = (int)blockIdx.x - KV_CTAS;   // 0..511
        const int b  = xb >> 6;
        const int rowblock = xb & 63;
        const int row0 = rowblock * 64;

#pragma unroll
        for (int i = 0; i < 8; i++) {
            const int rl = wid * 8 + i;
            const float* src = q + ((size_t)b * N_ + row0 + rl) * C_;
            float4 a = *(const float4*)(src + lane * 4);
            float4 c = *(const float4*)(src + 128 + lane * 4);
            *(float4*)&sq[rl * PSQ + lane * 4]       = a;
            *(float4*)&sq[rl * PSQ + 128 + lane * 4] = c;
            float ss = a.x * a.x + a.y * a.y + a.z * a.z + a.w * a.w
                     + c.x * c.x + c.y * c.y + c.z * c.z + c.w * c.w;
#pragma unroll
            for (int o = 16; o > 0; o >>= 1) ss += __shfl_xor_sync(0xffffffffu, ss, o);
            if (lane == 0) {
                float r = (ss > 1e-24f) ? rsqrtf(ss) : 1e12f;
                rn[rl] = r * (1.0f / (float)N_);
            }
        }
        __syncthreads();

        const int n_tile = rowblock >> 1;
        const int rt_hi  = (rowblock & 1) * 4;
        uint32_t* obase = g_qn + (size_t)(b * 32 + n_tile) * 32768;

#pragma unroll 1
        for (int it = 0; it < 16; it++) {
            const int bid = it * 8 + wid;
            const int km = bid >> 4, kk = (bid >> 2) & 3, rt = bid & 3;
            const int c0 = km * 32 + kk * 8 + tig;
            const int r0 = rt * 16 + g;
            const float s0 = rn[r0], s1 = rn[r0 + 8];
            uint4 o;
            o.x = f2tf(sq[r0 * PSQ + c0] * s0);
            o.y = f2tf(sq[(r0 + 8) * PSQ + c0] * s1);
            o.z = f2tf(sq[r0 * PSQ + c0 + 4] * s0);
            o.w = f2tf(sq[(r0 + 8) * PSQ + c0 + 4] * s1);
            *(uint4*)&obase[(size_t)(((km * 4 + kk) * 8 + rt_hi + rt) * 128) + lane * 4] = o;
        }
        return;
    }

    // ================= kv GEMM path =================
    uint32_t* As = sm;                        // [2][4096] packed A
    float*    Bs = (float*)(sm + 2 * 4096);   // [2][32*STA] raw fp32

    const int bid1 = blockIdx.x;              // 0..255
    const int d0 = (bid1 & 1) * 128;
    const int c0 = ((bid1 >> 1) & 1) * 128;
    const int bz = bid1 >> 2;                 // 0..63
    const int b  = bz >> 3;
    const int sp = bz & 7;
    const int m_base = sp * (KM_PER_SPLIT * 32);

    const int wc = (wid >> 2) * 64;
    const int wd = (wid & 3) * 32;
    const int lr = t >> 3;
    const int lq = (t & 7) * 4;

    const float* kb  = k + (size_t)b * M_ * C_;
    const float* vb  = v + (size_t)b * M_ * C_ + d0;
    const float* rkb = g_rk + b * M_;

    int kkA[4], ctA[4];
#pragma unroll
    for (int i = 0; i < 4; i++) { const int bd = wid * 4 + i; kkA[i] = bd >> 3; ctA[i] = bd & 7; }

    float pv[4][4];
    float pr[4][2];

#define KV_LOAD_A(m0) do { \
    _Pragma("unroll") \
    for (int i = 0; i < 4; i++) { \
        const int mr = (m0) + kkA[i] * 8 + tig; \
        const int cc = c0 + ctA[i] * 16 + g; \
        pv[i][0] = kb[(size_t)mr * C_ + cc]; \
        pv[i][1] = kb[(size_t)mr * C_ + cc + 8]; \
        pv[i][2] = kb[(size_t)(mr + 4) * C_ + cc]; \
        pv[i][3] = kb[(size_t)(mr + 4) * C_ + cc + 8]; \
        pr[i][0] = __ldg(rkb + mr); \
        pr[i][1] = __ldg(rkb + mr + 4); \
    } \
} while (0)

#define KV_STS_A(dst) do { \
    _Pragma("unroll") \
    for (int i = 0; i < 4; i++) { \
        uint4 o; \
        o.x = f2tf(pv[i][0] * pr[i][0]); \
        o.y = f2tf(pv[i][1] * pr[i][0]); \
        o.z = f2tf(pv[i][2] * pr[i][1]); \
        o.w = f2tf(pv[i][3] * pr[i][1]); \
        *(uint4*)&(dst)[(kkA[i] * 8 + ctA[i]) * 128 + lane * 4] = o; \
    } \
} while (0)

    KV_LOAD_A(m_base);
    KV_STS_A(As);
#pragma unroll
    for (int i = 0; i < 4; i++)
        cp16(&Bs[lr * STA + lq + i * 32], vb + (size_t)(m_base + lr) * C_ + lq + i * 32);
    cp_commit();
    KV_LOAD_A(m_base + 32);

    float acc[4][4][4] = {};

#pragma unroll 1
    for (int km = 0; km < KM_PER_SPLIT; km++) {
        const int cur = km & 1;
        const int nxt = cur ^ 1;
        if (km + 1 < KM_PER_SPLIT) {
            const int m0 = m_base + (km + 1) * 32;
            float* Bn = &Bs[nxt * 32 * STA];
#pragma unroll
            for (int i = 0; i < 4; i++)
                cp16(&Bn[lr * STA + lq + i * 32], vb + (size_t)(m0 + lr) * C_ + lq + i * 32);
            cp_commit();
            cp_wait<1>();
        } else {
            cp_wait<0>();
        }
        __syncthreads();

        const uint32_t* Ac = &As[cur * 4096];
        const float*    Bc = &Bs[cur * 32 * STA];
#pragma unroll
        for (int kk = 0; kk < 4; kk++) {
            const int k8 = kk * 8;
            uint32_t af[4][4];
            uint32_t bf[4][2];
#pragma unroll
            for (int mt = 0; mt < 4; mt++) {
                const int rt = (wid >> 2) * 4 + mt;
                const uint4 pk = *(const uint4*)&Ac[(kk * 8 + rt) * 128 + lane * 4];
                af[mt][0] = pk.x; af[mt][1] = pk.y; af[mt][2] = pk.z; af[mt][3] = pk.w;
            }
#pragma unroll
            for (int nt = 0; nt < 4; nt++) {
                const int col = wd + nt * 8 + g;
                bf[nt][0] = f2tf(Bc[(k8 + tig) * STA + col]);
                bf[nt][1] = f2tf(Bc[(k8 + tig + 4) * STA + col]);
            }
#pragma unroll
            for (int mt = 0; mt < 4; mt++)
#pragma unroll
                for (int nt = 0; nt < 4; nt++)
                    mma8(acc[mt][nt], af[mt], bf[nt]);
        }

        if (km + 1 < KM_PER_SPLIT) {
            KV_STS_A(&As[nxt * 4096]);
            if (km + 2 < KM_PER_SPLIT) KV_LOAD_A(m_base + (km + 2) * 32);
        }
        __syncthreads();
    }

    float* kvp = g_kvp + ((size_t)sp * B_ + b) * C_ * C_;
#pragma unroll
    for (int mt = 0; mt < 4; mt++)
#pragma unroll
        for (int nt = 0; nt < 4; nt++) {
            const int c = c0 + wc + mt * 16 + g;
            const int d = d0 + wd + nt * 8 + tig * 2;
            float2 v0 = make_float2(acc[mt][nt][0], acc[mt][nt][1]);
            float2 v1 = make_float2(acc[mt][nt][2], acc[mt][nt][3]);
            *(float2*)&kvp[(size_t)c * C_ + d]       = v0;
            *(float2*)&kvp[(size_t)(c + 8) * C_ + d] = v1;
        }
}

// ---------------------------------------------------------------------------
// Kernel 2b: reduce partials -> packed tf32 B-frags (R12-validated, 256 CTAs).
// ---------------------------------------------------------------------------
__global__ __launch_bounds__(256) void reduce_kernel() {
    __shared__ float rsm[32 * RST];
    const int dq = blockIdx.x;                 // 0..3 (64-d block)
    const int km = blockIdx.y;                 // 0..7 (32-c block)
    const int b  = blockIdx.z;
    const int t = threadIdx.x, lane = t & 31, wid = t >> 5;

#pragma unroll
    for (int p = 0; p < 2; p++) {
        const int idx = p * 256 + t;
        const int cl  = idx >> 4;
        const int dl4 = (idx & 15) * 4;
        float4 a = make_float4(0.f, 0.f, 0.f, 0.f);
#pragma unroll
        for (int sp = 0; sp < SPLITS; sp++) {
            const float4 x = *(const float4*)&g_kvp[((size_t)(sp * B_ + b) << 16)
                                                    + (size_t)(km * 32 + cl) * C_ + dq * 64 + dl4];
            a.x += x.x; a.y += x.y; a.z += x.z; a.w += x.w;
        }
        *(float4*)&rsm[cl * RST + dl4] = a;
    }
    __syncthreads();

    const int g = lane >> 2, tig = lane & 3;
    const int dt = dq >> 1;
#pragma unroll
    for (int j = 0; j < 4; j++) {
        const int combo = wid * 4 + j;
        const int kk    = combo & 3;
        const int d8tl  = combo >> 2;
        const int d8t   = (dq & 1) * 8 + d8tl;
        const int cl    = kk * 8 + tig;
        const int dl    = d8tl * 8 + g;
        uint2 o;
        o.x = f2tf(rsm[cl * RST + dl]);
        o.y = f2tf(rsm[(cl + 4) * RST + dl]);
        const int idx = (b << 15) | (dt << 14) | (km << 11) | (kk << 9)
                      | (d8t << 5) | lane;
        *(uint2*)&g_kv[(size_t)idx * 2] = o;
    }
}

// ---------------------------------------------------------------------------
// Kernel 3: ctx GEMM — R4/R6-validated 2-stage form (measured faster than
// the 3-stage ring: 32.9 vs 34.1 us).
// ---------------------------------------------------------------------------
__global__ __launch_bounds__(256, 2) void ctx_kernel(float* __restrict__ out) {
    extern __shared__ uint32_t sm[];
    uint32_t* As = sm;              // [2][4096]
    uint32_t* Bs = sm + 2 * 4096;   // [2][4096]

    const int b  = blockIdx.z;
    const int n_tile = blockIdx.y;
    const int dt = blockIdx.x;
    const int n0 = n_tile * 128;
    const int d0 = dt * 128;

    const int t = threadIdx.x, lane = t & 31, wid = t >> 5;
    const int g = lane >> 2, tig = lane & 3;
    const int wn = (wid >> 2) * 64;
    const int wd = (wid & 3) * 32;

    const uint32_t* qb  = g_qn + (size_t)(b * 32 + n_tile) * 32768;
    const uint32_t* kvb = g_kv + (size_t)(b * 2 + dt) * 32768;

    {
#pragma unroll
        for (int i = 0; i < 4; i++) {
            cp16(&As[t * 4 + i * 1024], qb + t * 4 + i * 1024);
            cp16(&Bs[t * 4 + i * 1024], kvb + t * 4 + i * 1024);
        }
        cp_commit();
    }

    float acc[4][4][4] = {};
    const int KM = C_ / 32;   // 8

#pragma unroll 1
    for (int km = 0; km < KM; km++) {
        const int cur = km & 1;
        if (km + 1 < KM) {
            const int nxt = cur ^ 1;
            const uint32_t* sA = qb  + (size_t)(km + 1) * 4096;
            const uint32_t* sB = kvb + (size_t)(km + 1) * 4096;
            uint32_t* An = &As[nxt * 4096];
            uint32_t* Bn = &Bs[nxt * 4096];
#pragma unroll
            for (int i = 0; i < 4; i++) {
                cp16(&An[t * 4 + i * 1024], sA + t * 4 + i * 1024);
                cp16(&Bn[t * 4 + i * 1024], sB + t * 4 + i * 1024);
            }
            cp_commit();
            cp_wait<1>();
        } else {
            cp_wait<0>();
        }
        __syncthreads();

        const uint32_t* Ac = &As[cur * 4096];
        const uint32_t* Bc = &Bs[cur * 4096];
#pragma unroll
        for (int kk = 0; kk < 4; kk++) {
            uint32_t af[4][4];
            uint32_t bf[4][2];
#pragma unroll
            for (int mt = 0; mt < 4; mt++) {
                const int rt = (wid >> 2) * 4 + mt;
                const uint4 pk = *(const uint4*)&Ac[(kk * 8 + rt) * 128 + lane * 4];
                af[mt][0] = pk.x; af[mt][1] = pk.y; af[mt][2] = pk.z; af[mt][3] = pk.w;
            }
#pragma unroll
            for (int nt = 0; nt < 4; nt++) {
                const int d8t = (wid & 3) * 4 + nt;
                const uint2 pk = *(const uint2*)&Bc[(kk * 16 + d8t) * 64 + lane * 2];
                bf[nt][0] = pk.x; bf[nt][1] = pk.y;
            }
#pragma unroll
            for (int mt = 0; mt < 4; mt++)
#pragma unroll
                for (int nt = 0; nt < 4; nt++)
                    mma8(acc[mt][nt], af[mt], bf[nt]);
        }
        __syncthreads();
    }

#pragma unroll
    for (int mt = 0; mt < 4; mt++)
#pragma unroll
        for (int nt = 0; nt < 4; nt++) {
            const int n = n0 + wn + mt * 16 + g;
            const int d = d0 + wd + nt * 8 + tig * 2;
            float2 v0 = make_float2(acc[mt][nt][0], acc[mt][nt][1]);
            float2 v1 = make_float2(acc[mt][nt][2], acc[mt][nt][3]);
            *(float2*)&out[((size_t)b * N_ + n) * C_ + d]       = v0;
            *(float2*)&out[((size_t)b * N_ + n + 8) * C_ + d]   = v1;
        }
}

// ---------------------------------------------------------------------------
extern "C" void kernel_launch(void* const* d_in, const int* in_sizes, int n_in,
                              void* d_out, int out_size) {
    const float* q = (const float*)d_in[0];
    const float* k = (const float*)d_in[1];
    const float* v = (const float*)d_in[2];
    float* out = (float*)d_out;

    const int smem_kvq = (2 * 4096 + 2 * 32 * STA) * 4;   // ~67.6 KB (>= qpack's 66.8)
    const int smem_ctx = (4 * 4096) * 4;                  // 64 KB
    cudaFuncSetAttribute(kvq_kernel, cudaFuncAttributeMaxDynamicSharedMemorySize, smem_kvq);
    cudaFuncSetAttribute(ctx_kernel, cudaFuncAttributeMaxDynamicSharedMemorySize, smem_ctx);

    // 1) k row norms (kv dependency)
    knorm_kernel<<<(B_ * M_) / 8, 256>>>(k);
    // 2) fused: kv split-K GEMM (CTAs 0..255) + q-pack (CTAs 256..767)
    kvq_kernel<<<KV_CTAS + 512, 256, smem_kvq>>>(k, v, q);
    // 2b) reduce partials -> packed tf32 kv
    reduce_kernel<<<dim3(4, 8, B_), 256>>>();
    // 3) out = qn @ kv (2-stage, validated fastest)
    ctx_kernel<<<dim3(C_ / 128, N_ / 128, B_), 256, smem_ctx>>>(out);
}